// round 1
// baseline (speedup 1.0000x reference)
#include <cuda_runtime.h>

#define NN   3072
#define H    8
#define DH   32
#define HIDD 256
#define DEG  16
#define EDGES (NN*DEG)
#define EDIM 32
#define FFND 1024

// ---------------- scratch (no allocations allowed) ----------------
__device__ float g_Q[NN*HIDD];
__device__ float g_K[NN*HIDD];
__device__ float g_V[NN*HIDD];
__device__ float g_attn[NN*HIDD];
__device__ float g_h1[NN*HIDD];
__device__ float g_ffn[NN*FFND];

// ---------------- packed f32x2 helpers ----------------
__device__ __forceinline__ unsigned long long pack2(float lo, float hi) {
    unsigned long long r;
    asm("mov.b64 %0,{%1,%2};" : "=l"(r) : "f"(lo), "f"(hi));
    return r;
}
__device__ __forceinline__ void fma2(unsigned long long &d, unsigned long long a, unsigned long long b) {
    asm("fma.rn.f32x2 %0, %1, %2, %0;" : "+l"(d) : "l"(a), "l"(b));
}
__device__ __forceinline__ float lo32(unsigned long long v) {
    return __uint_as_float((unsigned)(v & 0xffffffffull));
}
__device__ __forceinline__ float hi32(unsigned long long v) {
    return __uint_as_float((unsigned)(v >> 32));
}

// ---------------- generic row-blocked GEMM ----------------
// Block: 32 rows x 256 output cols, 256 threads (thread = one output column,
// 32 row-accumulators in registers, packed f32x2 FMAs).
// Optional epilogues: bias (always), RELU, residual add, LayerNorm over the
// full 256-wide row (requires gridDim.y==1 and ldOut==256).
template<int KTOT, bool RELU, bool LN, bool RES>
__global__ __launch_bounds__(256) void gemm32(
    const float* __restrict__ in,      // [rows, KTOT]
    const float* __restrict__ W,       // [KTOT, ldW]
    int ldW,
    const float* __restrict__ bias,    // [ldW]
    const float* __restrict__ res,     // [rows, ldOut] or null
    const float* __restrict__ ln_g,
    const float* __restrict__ ln_b,
    float* __restrict__ out,           // [rows, ldOut]
    int ldOut)
{
    __shared__ float xs[32][256];
    __shared__ float s_mu[32], s_rs[32];

    const int tid = threadIdx.x;
    const int r0  = blockIdx.x * 32;
    const int colOff = blockIdx.y * 256;
    const int j = colOff + tid;

    unsigned long long acc[32];
#pragma unroll
    for (int r = 0; r < 32; r++) acc[r] = 0ull;

    for (int kc = 0; kc < KTOT; kc += 256) {
        __syncthreads();
#pragma unroll 4
        for (int i = tid; i < 32 * 64; i += 256) {
            int r = i >> 6, c = i & 63;
            ((float4*)&xs[r][0])[c] = ((const float4*)(in + (size_t)(r0 + r) * KTOT + kc))[c];
        }
        __syncthreads();
#pragma unroll 1
        for (int k = 0; k < 256; k += 4) {
            const float* wp = W + (size_t)(kc + k) * ldW + j;
            float w0 = wp[0];
            float w1 = wp[ldW];
            float w2 = wp[2 * ldW];
            float w3 = wp[3 * ldW];
            unsigned long long w01 = pack2(w0, w1);
            unsigned long long w23 = pack2(w2, w3);
#pragma unroll
            for (int r = 0; r < 32; r++) {
                ulonglong2 xv = *(const ulonglong2*)&xs[r][k];  // {x_k,x_k+1},{x_k+2,x_k+3}
                fma2(acc[r], xv.x, w01);
                fma2(acc[r], xv.y, w23);
            }
        }
    }

    float y[32];
    const float bj = bias[j];
#pragma unroll
    for (int r = 0; r < 32; r++) {
        float v = lo32(acc[r]) + hi32(acc[r]) + bj;
        if (RES) v += res[(size_t)(r0 + r) * ldOut + j];
        if (RELU) v = fmaxf(v, 0.0f);
        y[r] = v;
    }

    if (!LN) {
#pragma unroll
        for (int r = 0; r < 32; r++)
            out[(size_t)(r0 + r) * ldOut + j] = y[r];
    } else {
        // full row (256 cols) lives in this block: LayerNorm epilogue
        __syncthreads();               // all k-loop smem reads done
#pragma unroll
        for (int r = 0; r < 32; r++) xs[r][tid] = y[r];
        __syncthreads();
        const int w = tid >> 5, lane = tid & 31;
        for (int r = w; r < 32; r += 8) {
            float s = 0.f, s2 = 0.f;
#pragma unroll
            for (int c = lane; c < 256; c += 32) {
                float v = xs[r][c];
                s += v; s2 += v * v;
            }
#pragma unroll
            for (int o = 16; o; o >>= 1) {
                s  += __shfl_xor_sync(0xffffffffu, s,  o);
                s2 += __shfl_xor_sync(0xffffffffu, s2, o);
            }
            if (lane == 0) {
                float m = s * (1.0f / 256.0f);
                float var = fmaxf(s2 * (1.0f / 256.0f) - m * m, 0.0f);
                s_mu[r] = m;
                s_rs[r] = rsqrtf(var + 1e-5f);
            }
        }
        __syncthreads();
        const float gj = ln_g[tid], bbj = ln_b[tid];
#pragma unroll
        for (int r = 0; r < 32; r++)
            out[(size_t)(r0 + r) * 256 + tid] = (xs[r][tid] - s_mu[r]) * s_rs[r] * gj + bbj;
    }
}

// ---------------- sparse neighbor attention (+ fused edge-bias GEMM) -------
// One block per node, 256 threads.
//  phase 1 (threads 0..127, thread = (h,d)): score = q_h . k_h(s_d)/sqrt(Dh)
//     + edge_features[n,d] @ We[:,h] + be[h]; duplicate sources keep only the
//     LAST occurrence (matches jax scatter last-write-wins + single mask bit);
//     softmax over 16-lane groups.
//  phase 2 (all 256 threads, thread = (h,k)): out = sum_d a[h,d] * V[s_d,h,k]
__global__ __launch_bounds__(256) void attn_kernel(
    const int*   __restrict__ neighbors,
    const float* __restrict__ ef,
    const float* __restrict__ We,     // [EDIM, H]
    const float* __restrict__ be,
    const float* __restrict__ Q,
    const float* __restrict__ K,
    const float* __restrict__ V,
    float* __restrict__ outp)
{
    const int n = blockIdx.x;
    const int tid = threadIdx.x;
    __shared__ float q[HIDD];
    __shared__ int nbr[DEG];
    __shared__ float attw[H][DEG];

    if (tid < DEG) nbr[tid] = neighbors[n * DEG + tid];
    q[tid] = Q[(size_t)n * HIDD + tid];
    __syncthreads();

    if (tid < H * DEG) {
        const int h = tid >> 4, d = tid & 15;
        const int s = nbr[d];
        bool keep = true;
#pragma unroll
        for (int d2 = 0; d2 < DEG; d2++)
            if (d2 > d && nbr[d2] == s) keep = false;

        float sc = -1e30f;
        if (keep) {
            const float4* kv = (const float4*)(K + (size_t)s * HIDD + h * DH);
            const float4* qh = (const float4*)(q + h * DH);
            float acc = 0.f;
#pragma unroll
            for (int k = 0; k < 8; k++) {
                float4 a = qh[k], b = kv[k];
                acc += a.x * b.x + a.y * b.y + a.z * b.z + a.w * b.w;
            }
            const float4* ep = (const float4*)(ef + (size_t)(n * DEG + d) * EDIM);
            float bias_acc = 0.f;
#pragma unroll
            for (int k = 0; k < 8; k++) {
                float4 e4 = ep[k];
                bias_acc += e4.x * We[(k * 4 + 0) * H + h];
                bias_acc += e4.y * We[(k * 4 + 1) * H + h];
                bias_acc += e4.z * We[(k * 4 + 2) * H + h];
                bias_acc += e4.w * We[(k * 4 + 3) * H + h];
            }
            sc = acc * 0.17677669529663687f + bias_acc + be[h];
        }
        // softmax over groups of 16 lanes (one head per half-warp)
        float m = sc;
#pragma unroll
        for (int o = 8; o; o >>= 1) m = fmaxf(m, __shfl_xor_sync(0xffffffffu, m, o, 16));
        float e = keep ? expf(sc - m) : 0.0f;
        float ssum = e;
#pragma unroll
        for (int o = 8; o; o >>= 1) ssum += __shfl_xor_sync(0xffffffffu, ssum, o, 16);
        attw[h][d] = e / ssum;
    }
    __syncthreads();

    {
        const int h = tid >> 5, k = tid & 31;
        float acc = 0.f;
#pragma unroll
        for (int d = 0; d < DEG; d++)
            acc += attw[h][d] * V[(size_t)nbr[d] * HIDD + h * DH + k];
        outp[(size_t)n * HIDD + tid] = acc;
    }
}

// ---------------- launch ----------------
extern "C" void kernel_launch(void* const* d_in, const int* in_sizes, int n_in,
                              void* d_out, int out_size)
{
    const float* x    = (const float*)d_in[0];
    const int*   nb   = (const int*)  d_in[1];
    const float* ef   = (const float*)d_in[2];
    const float* Wq   = (const float*)d_in[3];
    const float* bq   = (const float*)d_in[4];
    const float* Wk   = (const float*)d_in[5];
    const float* bk   = (const float*)d_in[6];
    const float* Wv   = (const float*)d_in[7];
    const float* bv   = (const float*)d_in[8];
    const float* We   = (const float*)d_in[9];
    const float* be   = (const float*)d_in[10];
    const float* Wo   = (const float*)d_in[11];
    const float* bo   = (const float*)d_in[12];
    const float* ln1g = (const float*)d_in[13];
    const float* ln1b = (const float*)d_in[14];
    const float* ln2g = (const float*)d_in[15];
    const float* ln2b = (const float*)d_in[16];
    const float* Wf1  = (const float*)d_in[17];
    const float* bf1  = (const float*)d_in[18];
    const float* Wf2  = (const float*)d_in[19];
    const float* bf2  = (const float*)d_in[20];
    float* out = (float*)d_out;

    float *pQ, *pK, *pV, *pA, *pH1, *pF;
    cudaGetSymbolAddress((void**)&pQ,  g_Q);
    cudaGetSymbolAddress((void**)&pK,  g_K);
    cudaGetSymbolAddress((void**)&pV,  g_V);
    cudaGetSymbolAddress((void**)&pA,  g_attn);
    cudaGetSymbolAddress((void**)&pH1, g_h1);
    cudaGetSymbolAddress((void**)&pF,  g_ffn);

    const int RB = NN / 32;  // 96 row blocks

    // QKV projections
    gemm32<256, false, false, false><<<RB, 256>>>(x, Wq, 256, bq, nullptr, nullptr, nullptr, pQ, 256);
    gemm32<256, false, false, false><<<RB, 256>>>(x, Wk, 256, bk, nullptr, nullptr, nullptr, pK, 256);
    gemm32<256, false, false, false><<<RB, 256>>>(x, Wv, 256, bv, nullptr, nullptr, nullptr, pV, 256);

    // sparse attention with fused edge-bias projection
    attn_kernel<<<NN, 256>>>(nb, ef, We, be, pQ, pK, pV, pA);

    // Wo + bias + residual + LN1 -> h1
    gemm32<256, false, true, true><<<RB, 256>>>(pA, Wo, 256, bo, x, ln1g, ln1b, pH1, 256);

    // FFN up + ReLU
    gemm32<256, true, false, false><<<dim3(RB, 4), 256>>>(pH1, Wf1, 1024, bf1, nullptr, nullptr, nullptr, pF, 1024);

    // FFN down + bias + residual + LN2 -> d_out
    gemm32<1024, false, true, true><<<RB, 256>>>(pF, Wf2, 256, bf2, pH1, ln2g, ln2b, out, 256);
}

// round 2
// speedup vs baseline: 2.4556x; 2.4556x over previous
#include <cuda_runtime.h>

#define NN   3072
#define H    8
#define DH   32
#define HIDD 256
#define DEG  16
#define EDIM 32
#define FFND 1024

// ---------------- scratch (no allocations allowed) ----------------
__device__ float g_Q[NN*HIDD];
__device__ float g_K[NN*HIDD];
__device__ float g_V[NN*HIDD];
__device__ float g_attn[NN*HIDD];
__device__ float g_h1[NN*HIDD];
__device__ float g_ffn[NN*FFND];

// ---------------- tf32 helpers ----------------
__device__ __forceinline__ float to_tf32(float x) {
    unsigned u;
    asm("cvt.rna.tf32.f32 %0, %1;" : "=r"(u) : "f"(x));
    return __uint_as_float(u);
}

__device__ __forceinline__ void mma_tf32(float* c, const unsigned* a, const unsigned* b) {
    asm volatile(
        "mma.sync.aligned.m16n8k8.row.col.f32.tf32.tf32.f32 "
        "{%0,%1,%2,%3},{%4,%5,%6,%7},{%8,%9},{%0,%1,%2,%3};"
        : "+f"(c[0]), "+f"(c[1]), "+f"(c[2]), "+f"(c[3])
        : "r"(a[0]), "r"(a[1]), "r"(a[2]), "r"(a[3]), "r"(b[0]), "r"(b[1]));
}

// ---------------- tf32 tensor-core GEMM ----------------
// out[rows, ldW] = in[rows, KTOT] @ W[KTOT, ldW] + bias, optional ReLU.
// Block tile 64x64, 8 warps (4 M x 2 N), warp tile 16x32, K-chunk 32.
// Smem pitches chosen so fragment LDS are bank-conflict-free:
//   A_s pitch 36:  bank = (36*(g)+l)%32 = (4g+l)%32  -> 32 distinct
//   B_s pitch 72:  bank = (72*l+g)%32   = (8l+g)%32  -> 32 distinct
template<bool RELU>
__global__ __launch_bounds__(256) void gemm_tc(
    const float* __restrict__ in,
    const float* __restrict__ W,
    const float* __restrict__ bias,
    float* __restrict__ out,
    int KTOT, int ldW)
{
    constexpr int LA = 36;
    constexpr int LB = 72;
    __shared__ float As[64 * LA];
    __shared__ float Bs[32 * LB];

    const int tid  = threadIdx.x;
    const int warp = tid >> 5;
    const int lane = tid & 31;
    const int g    = lane >> 2;       // group id 0..7
    const int l    = lane & 3;        // thread-in-group 0..3
    const int wm   = warp & 3;        // warp row 0..3
    const int wn   = warp >> 2;       // warp col 0..1

    const int r0  = blockIdx.x * 64;
    const int cb0 = blockIdx.y * 64;

    float c[4][4];
#pragma unroll
    for (int j = 0; j < 4; j++)
#pragma unroll
        for (int q = 0; q < 4; q++) c[j][q] = 0.f;

    // prefetch registers
    float4 av[2], bv[2];
    const int am = tid >> 3, ac4 = tid & 7;        // A: row am / am+32, 4-col group ac4
    const int bk = tid >> 4, bc4 = tid & 15;       // B: k-row bk / bk+16, 4-col group bc4

    auto loadA = [&](int kc) {
        av[0] = *(const float4*)(in + (size_t)(r0 + am)      * KTOT + kc + ac4 * 4);
        av[1] = *(const float4*)(in + (size_t)(r0 + am + 32) * KTOT + kc + ac4 * 4);
    };
    auto loadB = [&](int kc) {
        bv[0] = *(const float4*)(W + (size_t)(kc + bk)      * ldW + cb0 + bc4 * 4);
        bv[1] = *(const float4*)(W + (size_t)(kc + bk + 16) * ldW + cb0 + bc4 * 4);
    };
    auto stage = [&]() {
        float4 t;
        t = av[0];
        *(float4*)&As[am * LA + ac4 * 4] =
            make_float4(to_tf32(t.x), to_tf32(t.y), to_tf32(t.z), to_tf32(t.w));
        t = av[1];
        *(float4*)&As[(am + 32) * LA + ac4 * 4] =
            make_float4(to_tf32(t.x), to_tf32(t.y), to_tf32(t.z), to_tf32(t.w));
        t = bv[0];
        *(float4*)&Bs[bk * LB + bc4 * 4] =
            make_float4(to_tf32(t.x), to_tf32(t.y), to_tf32(t.z), to_tf32(t.w));
        t = bv[1];
        *(float4*)&Bs[(bk + 16) * LB + bc4 * 4] =
            make_float4(to_tf32(t.x), to_tf32(t.y), to_tf32(t.z), to_tf32(t.w));
    };

    const int NC = KTOT >> 5;
    loadA(0); loadB(0);

    for (int ch = 0; ch < NC; ch++) {
        __syncthreads();
        stage();
        __syncthreads();
        if (ch + 1 < NC) { loadA((ch + 1) << 5); loadB((ch + 1) << 5); }

#pragma unroll
        for (int ks = 0; ks < 4; ks++) {
            const int k0 = ks * 8;
            unsigned a[4];
            const int ar = wm * 16 + g;
            a[0] = __float_as_uint(As[ar * LA + k0 + l]);
            a[1] = __float_as_uint(As[(ar + 8) * LA + k0 + l]);
            a[2] = __float_as_uint(As[ar * LA + k0 + l + 4]);
            a[3] = __float_as_uint(As[(ar + 8) * LA + k0 + l + 4]);
#pragma unroll
            for (int j = 0; j < 4; j++) {
                unsigned b[2];
                const int bc = wn * 32 + j * 8 + g;
                b[0] = __float_as_uint(Bs[(k0 + l) * LB + bc]);
                b[1] = __float_as_uint(Bs[(k0 + l + 4) * LB + bc]);
                mma_tf32(c[j], a, b);
            }
        }
    }

    // epilogue: bias (+ReLU), float2 stores
    const int row0 = r0 + wm * 16 + g;
#pragma unroll
    for (int j = 0; j < 4; j++) {
        const int col = cb0 + wn * 32 + j * 8 + l * 2;
        const float b0 = bias[col], b1 = bias[col + 1];
        float v00 = c[j][0] + b0, v01 = c[j][1] + b1;
        float v10 = c[j][2] + b0, v11 = c[j][3] + b1;
        if (RELU) {
            v00 = fmaxf(v00, 0.f); v01 = fmaxf(v01, 0.f);
            v10 = fmaxf(v10, 0.f); v11 = fmaxf(v11, 0.f);
        }
        *(float2*)&out[(size_t)row0 * ldW + col]       = make_float2(v00, v01);
        *(float2*)&out[(size_t)(row0 + 8) * ldW + col] = make_float2(v10, v11);
    }
}

// ---------------- residual + LayerNorm (warp per row, 256-wide rows) -------
__global__ __launch_bounds__(256) void ln_res_kernel(
    const float* __restrict__ y,
    const float* __restrict__ res,
    const float* __restrict__ lg,
    const float* __restrict__ lb,
    float* __restrict__ out)
{
    const int warp = threadIdx.x >> 5, lane = threadIdx.x & 31;
    const int row = blockIdx.x * 8 + warp;
    const float4* yp = (const float4*)(y   + (size_t)row * HIDD);
    const float4* rp = (const float4*)(res + (size_t)row * HIDD);

    float4 v0 = yp[lane],      r0 = rp[lane];
    float4 v1 = yp[lane + 32], r1 = rp[lane + 32];
    v0.x += r0.x; v0.y += r0.y; v0.z += r0.z; v0.w += r0.w;
    v1.x += r1.x; v1.y += r1.y; v1.z += r1.z; v1.w += r1.w;

    float s  = v0.x + v0.y + v0.z + v0.w + v1.x + v1.y + v1.z + v1.w;
    float s2 = v0.x*v0.x + v0.y*v0.y + v0.z*v0.z + v0.w*v0.w
             + v1.x*v1.x + v1.y*v1.y + v1.z*v1.z + v1.w*v1.w;
#pragma unroll
    for (int o = 16; o; o >>= 1) {
        s  += __shfl_xor_sync(0xffffffffu, s,  o);
        s2 += __shfl_xor_sync(0xffffffffu, s2, o);
    }
    const float mu = s * (1.f / 256.f);
    const float var = fmaxf(s2 * (1.f / 256.f) - mu * mu, 0.f);
    const float rs = rsqrtf(var + 1e-5f);

    const float4* gp = (const float4*)lg;
    const float4* bp = (const float4*)lb;
    float4 g0 = gp[lane], g1 = gp[lane + 32];
    float4 b0 = bp[lane], b1 = bp[lane + 32];
    float4 o0, o1;
    o0.x = (v0.x - mu) * rs * g0.x + b0.x;  o0.y = (v0.y - mu) * rs * g0.y + b0.y;
    o0.z = (v0.z - mu) * rs * g0.z + b0.z;  o0.w = (v0.w - mu) * rs * g0.w + b0.w;
    o1.x = (v1.x - mu) * rs * g1.x + b1.x;  o1.y = (v1.y - mu) * rs * g1.y + b1.y;
    o1.z = (v1.z - mu) * rs * g1.z + b1.z;  o1.w = (v1.w - mu) * rs * g1.w + b1.w;
    ((float4*)(out + (size_t)row * HIDD))[lane]      = o0;
    ((float4*)(out + (size_t)row * HIDD))[lane + 32] = o1;
}

// ---------------- sparse neighbor attention (+ fused edge-bias GEMM) -------
__global__ __launch_bounds__(256) void attn_kernel(
    const int*   __restrict__ neighbors,
    const float* __restrict__ ef,
    const float* __restrict__ We,     // [EDIM, H]
    const float* __restrict__ be,
    const float* __restrict__ Q,
    const float* __restrict__ K,
    const float* __restrict__ V,
    float* __restrict__ outp)
{
    const int n = blockIdx.x;
    const int tid = threadIdx.x;
    __shared__ float q[HIDD];
    __shared__ int nbr[DEG];
    __shared__ float attw[H][DEG];

    if (tid < DEG) nbr[tid] = neighbors[n * DEG + tid];
    q[tid] = Q[(size_t)n * HIDD + tid];
    __syncthreads();

    if (tid < H * DEG) {
        const int h = tid >> 4, d = tid & 15;
        const int s = nbr[d];
        bool keep = true;
#pragma unroll
        for (int d2 = 0; d2 < DEG; d2++)
            if (d2 > d && nbr[d2] == s) keep = false;

        float sc = -1e30f;
        if (keep) {
            const float4* kv = (const float4*)(K + (size_t)s * HIDD + h * DH);
            const float4* qh = (const float4*)(q + h * DH);
            float acc = 0.f;
#pragma unroll
            for (int k = 0; k < 8; k++) {
                float4 a = qh[k], b = kv[k];
                acc += a.x * b.x + a.y * b.y + a.z * b.z + a.w * b.w;
            }
            const float4* ep = (const float4*)(ef + (size_t)(n * DEG + d) * EDIM);
            float bias_acc = 0.f;
#pragma unroll
            for (int k = 0; k < 8; k++) {
                float4 e4 = ep[k];
                bias_acc += e4.x * We[(k * 4 + 0) * H + h];
                bias_acc += e4.y * We[(k * 4 + 1) * H + h];
                bias_acc += e4.z * We[(k * 4 + 2) * H + h];
                bias_acc += e4.w * We[(k * 4 + 3) * H + h];
            }
            sc = acc * 0.17677669529663687f + bias_acc + be[h];
        }
        float m = sc;
#pragma unroll
        for (int o = 8; o; o >>= 1) m = fmaxf(m, __shfl_xor_sync(0xffffffffu, m, o, 16));
        float e = keep ? expf(sc - m) : 0.0f;
        float ssum = e;
#pragma unroll
        for (int o = 8; o; o >>= 1) ssum += __shfl_xor_sync(0xffffffffu, ssum, o, 16);
        attw[h][d] = e / ssum;
    }
    __syncthreads();

    {
        const int h = tid >> 5, k = tid & 31;
        float acc = 0.f;
#pragma unroll
        for (int d = 0; d < DEG; d++)
            acc += attw[h][d] * V[(size_t)nbr[d] * HIDD + h * DH + k];
        outp[(size_t)n * HIDD + tid] = acc;
    }
}

// ---------------- launch ----------------
extern "C" void kernel_launch(void* const* d_in, const int* in_sizes, int n_in,
                              void* d_out, int out_size)
{
    const float* x    = (const float*)d_in[0];
    const int*   nb   = (const int*)  d_in[1];
    const float* ef   = (const float*)d_in[2];
    const float* Wq   = (const float*)d_in[3];
    const float* bq   = (const float*)d_in[4];
    const float* Wk   = (const float*)d_in[5];
    const float* bk   = (const float*)d_in[6];
    const float* Wv   = (const float*)d_in[7];
    const float* bv   = (const float*)d_in[8];
    const float* We   = (const float*)d_in[9];
    const float* be   = (const float*)d_in[10];
    const float* Wo   = (const float*)d_in[11];
    const float* bo   = (const float*)d_in[12];
    const float* ln1g = (const float*)d_in[13];
    const float* ln1b = (const float*)d_in[14];
    const float* ln2g = (const float*)d_in[15];
    const float* ln2b = (const float*)d_in[16];
    const float* Wf1  = (const float*)d_in[17];
    const float* bf1  = (const float*)d_in[18];
    const float* Wf2  = (const float*)d_in[19];
    const float* bf2  = (const float*)d_in[20];
    float* out = (float*)d_out;

    float *pQ, *pK, *pV, *pA, *pH1, *pF;
    cudaGetSymbolAddress((void**)&pQ,  g_Q);
    cudaGetSymbolAddress((void**)&pK,  g_K);
    cudaGetSymbolAddress((void**)&pV,  g_V);
    cudaGetSymbolAddress((void**)&pA,  g_attn);
    cudaGetSymbolAddress((void**)&pH1, g_h1);
    cudaGetSymbolAddress((void**)&pF,  g_ffn);

    const dim3 gQKV(NN / 64, HIDD / 64);   // 48 x 4
    const dim3 gF1 (NN / 64, FFND / 64);   // 48 x 16

    // QKV projections (tf32 tensor cores)
    gemm_tc<false><<<gQKV, 256>>>(x, Wq, bq, pQ, HIDD, HIDD);
    gemm_tc<false><<<gQKV, 256>>>(x, Wk, bk, pK, HIDD, HIDD);
    gemm_tc<false><<<gQKV, 256>>>(x, Wv, bv, pV, HIDD, HIDD);

    // sparse attention with fused edge-bias projection
    attn_kernel<<<NN, 256>>>(nb, ef, We, be, pQ, pK, pV, pA);

    // Wo (raw, into pK which is now free), then residual + LN1 -> h1
    gemm_tc<false><<<gQKV, 256>>>(pA, Wo, bo, pK, HIDD, HIDD);
    ln_res_kernel<<<NN / 8, 256>>>(pK, x, ln1g, ln1b, pH1);

    // FFN up + ReLU
    gemm_tc<true><<<gF1, 256>>>(pH1, Wf1, bf1, pF, HIDD, FFND);

    // FFN down (raw, into pQ which is free), then residual + LN2 -> out
    gemm_tc<false><<<gQKV, 256>>>(pF, Wf2, bf2, pQ, FFND, HIDD);
    ln_res_kernel<<<NN / 8, 256>>>(pQ, pH1, ln2g, ln2b, out);
}

// round 3
// speedup vs baseline: 2.9483x; 1.2006x over previous
#include <cuda_runtime.h>

#define NN   3072
#define H    8
#define DH   32
#define HIDD 256
#define DEG  16
#define EDIM 32
#define FFND 1024
#define EE   (NN*DEG)

// ---------------- scratch (no allocations allowed) ----------------
__device__ float g_Q[NN*HIDD];
__device__ float g_K[NN*HIDD];
__device__ float g_V[NN*HIDD];
__device__ float g_attn[NN*HIDD];
__device__ float g_h1[NN*HIDD];
__device__ float g_ffn[NN*FFND];
__device__ float g_ea[H*EE];          // edge bias, head-major [h][e]

// ---------------- tf32 helpers ----------------
__device__ __forceinline__ float to_tf32(float x) {
    unsigned u;
    asm("cvt.rna.tf32.f32 %0, %1;" : "=r"(u) : "f"(x));
    return __uint_as_float(u);
}
__device__ __forceinline__ void mma_tf32(float* c, const unsigned* a, const unsigned* b) {
    asm volatile(
        "mma.sync.aligned.m16n8k8.row.col.f32.tf32.tf32.f32 "
        "{%0,%1,%2,%3},{%4,%5,%6,%7},{%8,%9},{%0,%1,%2,%3};"
        : "+f"(c[0]), "+f"(c[1]), "+f"(c[2]), "+f"(c[3])
        : "r"(a[0]), "r"(a[1]), "r"(a[2]), "r"(a[3]), "r"(b[0]), "r"(b[1]));
}

constexpr int LA = 36;   // A smem pitch: bank = (4g+l)%32 -> conflict-free
constexpr int LB = 72;   // B smem pitch: bank = (8l+g)%32 -> conflict-free
constexpr int ASZ = 64 * LA;
constexpr int BSZ = 32 * LB;

// ---------------- tf32 tensor-core GEMM body (double-buffered) ----------------
// Block tile 64x64, 8 warps (4M x 2N), warp tile 16x32, K-chunk 32,
// 2-stage smem pipeline: one __syncthreads per chunk.
template<bool RELU>
__device__ __forceinline__ void gemm_body(
    const float* __restrict__ in,
    const float* __restrict__ W,
    const float* __restrict__ bias,
    float* __restrict__ out,
    int KTOT, int ldW, int r0, int cb0,
    float* As, float* Bs)
{
    const int tid  = threadIdx.x;
    const int warp = tid >> 5;
    const int lane = tid & 31;
    const int g    = lane >> 2;
    const int l    = lane & 3;
    const int wm   = warp & 3;
    const int wn   = warp >> 2;

    float c[4][4];
#pragma unroll
    for (int j = 0; j < 4; j++)
#pragma unroll
        for (int q = 0; q < 4; q++) c[j][q] = 0.f;

    float4 av[2], bv[2];
    const int am = tid >> 3, ac4 = tid & 7;
    const int bk = tid >> 4, bc4 = tid & 15;

    auto loadA = [&](int kc) {
        av[0] = *(const float4*)(in + (size_t)(r0 + am)      * KTOT + kc + ac4 * 4);
        av[1] = *(const float4*)(in + (size_t)(r0 + am + 32) * KTOT + kc + ac4 * 4);
    };
    auto loadB = [&](int kc) {
        bv[0] = *(const float4*)(W + (size_t)(kc + bk)      * ldW + cb0 + bc4 * 4);
        bv[1] = *(const float4*)(W + (size_t)(kc + bk + 16) * ldW + cb0 + bc4 * 4);
    };
    auto stage = [&](int st) {
        float* Ad = As + st * ASZ;
        float* Bd = Bs + st * BSZ;
        float4 t;
        t = av[0];
        *(float4*)&Ad[am * LA + ac4 * 4] =
            make_float4(to_tf32(t.x), to_tf32(t.y), to_tf32(t.z), to_tf32(t.w));
        t = av[1];
        *(float4*)&Ad[(am + 32) * LA + ac4 * 4] =
            make_float4(to_tf32(t.x), to_tf32(t.y), to_tf32(t.z), to_tf32(t.w));
        t = bv[0];
        *(float4*)&Bd[bk * LB + bc4 * 4] =
            make_float4(to_tf32(t.x), to_tf32(t.y), to_tf32(t.z), to_tf32(t.w));
        t = bv[1];
        *(float4*)&Bd[(bk + 16) * LB + bc4 * 4] =
            make_float4(to_tf32(t.x), to_tf32(t.y), to_tf32(t.z), to_tf32(t.w));
    };

    const int NC = KTOT >> 5;
    loadA(0); loadB(0);
    stage(0);

    for (int ch = 0; ch < NC; ch++) {
        if (ch + 1 < NC) { loadA((ch + 1) << 5); loadB((ch + 1) << 5); }
        __syncthreads();
        const float* Ac = As + (ch & 1) * ASZ;
        const float* Bc = Bs + (ch & 1) * BSZ;
#pragma unroll
        for (int ks = 0; ks < 4; ks++) {
            const int k0 = ks * 8;
            unsigned a[4];
            const int ar = wm * 16 + g;
            a[0] = __float_as_uint(Ac[ar * LA + k0 + l]);
            a[1] = __float_as_uint(Ac[(ar + 8) * LA + k0 + l]);
            a[2] = __float_as_uint(Ac[ar * LA + k0 + l + 4]);
            a[3] = __float_as_uint(Ac[(ar + 8) * LA + k0 + l + 4]);
#pragma unroll
            for (int j = 0; j < 4; j++) {
                unsigned b[2];
                const int bc = wn * 32 + j * 8 + g;
                b[0] = __float_as_uint(Bc[(k0 + l) * LB + bc]);
                b[1] = __float_as_uint(Bc[(k0 + l + 4) * LB + bc]);
                mma_tf32(c[j], a, b);
            }
        }
        if (ch + 1 < NC) stage((ch + 1) & 1);
    }

    const int row0 = r0 + wm * 16 + g;
#pragma unroll
    for (int j = 0; j < 4; j++) {
        const int col = cb0 + wn * 32 + j * 8 + l * 2;
        const float b0 = bias[col], b1 = bias[col + 1];
        float v00 = c[j][0] + b0, v01 = c[j][1] + b1;
        float v10 = c[j][2] + b0, v11 = c[j][3] + b1;
        if (RELU) {
            v00 = fmaxf(v00, 0.f); v01 = fmaxf(v01, 0.f);
            v10 = fmaxf(v10, 0.f); v11 = fmaxf(v11, 0.f);
        }
        *(float2*)&out[(size_t)row0 * ldW + col]       = make_float2(v00, v01);
        *(float2*)&out[(size_t)(row0 + 8) * ldW + col] = make_float2(v10, v11);
    }
}

template<bool RELU>
__global__ __launch_bounds__(256) void gemm_tc(
    const float* __restrict__ in, const float* __restrict__ W,
    const float* __restrict__ bias, float* __restrict__ out,
    int KTOT, int ldW)
{
    __shared__ float As[2 * ASZ];
    __shared__ float Bs[2 * BSZ];
    gemm_body<RELU>(in, W, bias, out, KTOT, ldW,
                    blockIdx.x * 64, blockIdx.y * 64, As, Bs);
}

// fused QKV: blockIdx.y in [0,12): y>>2 selects matrix, y&3 selects col tile
__global__ __launch_bounds__(256) void gemm_qkv(
    const float* __restrict__ x,
    const float* __restrict__ Wq, const float* __restrict__ bq, float* __restrict__ oq,
    const float* __restrict__ Wk, const float* __restrict__ bk, float* __restrict__ ok,
    const float* __restrict__ Wv, const float* __restrict__ bv, float* __restrict__ ov)
{
    __shared__ float As[2 * ASZ];
    __shared__ float Bs[2 * BSZ];
    const int sel = blockIdx.y >> 2;
    const float* W = (sel == 0) ? Wq : (sel == 1) ? Wk : Wv;
    const float* b = (sel == 0) ? bq : (sel == 1) ? bk : bv;
    float*       o = (sel == 0) ? oq : (sel == 1) ? ok : ov;
    gemm_body<false>(x, W, b, o, HIDD, HIDD,
                     blockIdx.x * 64, (blockIdx.y & 3) * 64, As, Bs);
}

// ---------------- edge bias: ea[h][e] = ef[e,:] @ We[:,h] + be[h] ----------
__global__ __launch_bounds__(256) void edge_kernel(
    const float* __restrict__ ef,     // [E, 32]
    const float* __restrict__ We,     // [32, 8]
    const float* __restrict__ be,     // [8]
    float* __restrict__ ea)           // [8, E]
{
    __shared__ float efs[32][33];
    __shared__ float Wes[256];
    const int tid = threadIdx.x;
    const int e0 = blockIdx.x * 32;

#pragma unroll
    for (int i = 0; i < 4; i++) {
        int lin = i * 256 + tid;
        efs[lin >> 5][lin & 31] = ef[(size_t)e0 * 32 + lin];
    }
    Wes[tid] = We[tid];
    __syncthreads();

    const int h = tid >> 5, el = tid & 31;
    float acc = be[h];
#pragma unroll
    for (int k = 0; k < 32; k++)
        acc = fmaf(efs[el][k], Wes[k * 8 + h], acc);
    ea[(size_t)h * EE + e0 + el] = acc;
}

// ---------------- attention: warp per (node, head), coalesced slices -------
__global__ __launch_bounds__(256) void attn2(
    const int*   __restrict__ neighbors,
    const float* __restrict__ ea,     // [8, E]
    const float* __restrict__ be,
    const float* __restrict__ Q,
    const float* __restrict__ K,
    const float* __restrict__ V,
    float* __restrict__ outp)
{
    const int n = blockIdx.x;
    const int h = threadIdx.x >> 5;
    const int lane = threadIdx.x & 31;
    const unsigned FULL = 0xffffffffu;

    __shared__ int s_nbr[DEG];
    __shared__ unsigned s_keep;

    if (h == 0) {
        int v = (lane < DEG) ? neighbors[n * DEG + lane] : -1;
        bool keep = (lane < DEG);
#pragma unroll
        for (int d2 = 1; d2 < DEG; d2++) {
            int other = __shfl_sync(FULL, v, d2);
            if (d2 > lane && other == v) keep = false;
        }
        unsigned km = __ballot_sync(FULL, keep && lane < DEG);
        if (lane < DEG) s_nbr[lane] = v;
        if (lane == 0) s_keep = km;
    }
    __syncthreads();

    const int nb_l = (lane < DEG) ? s_nbr[lane] : 0;
    const unsigned km = s_keep;
    const float q = Q[(size_t)n * HIDD + h * DH + lane];

    // --- scores: 16 coalesced K-slice loads (MLP=16), then shfl reductions
    float kv[DEG];
#pragma unroll
    for (int d = 0; d < DEG; d++) {
        int s = __shfl_sync(FULL, nb_l, d);
        kv[d] = K[(size_t)s * HIDD + h * DH + lane];
    }
    float myscore = -1e30f;
#pragma unroll
    for (int d = 0; d < DEG; d++) {
        float p = q * kv[d];
#pragma unroll
        for (int o = 16; o; o >>= 1) p += __shfl_xor_sync(FULL, p, o);
        if (lane == d) myscore = p;
    }

    const bool keep = (lane < DEG) && ((km >> lane) & 1u);
    float bias = (lane < DEG) ? ea[(size_t)h * EE + n * DEG + lane] : 0.f;
    myscore = keep ? fmaf(myscore, 0.17677669529663687f, bias + be[h]) : -1e30f;

    // --- softmax across the warp (invalid lanes at -1e30 / 0)
    float m = myscore;
#pragma unroll
    for (int o = 16; o; o >>= 1) m = fmaxf(m, __shfl_xor_sync(FULL, m, o));
    float e = keep ? expf(myscore - m) : 0.f;
    float ssum = e;
#pragma unroll
    for (int o = 16; o; o >>= 1) ssum += __shfl_xor_sync(FULL, ssum, o);
    const float w = e / ssum;

    // --- output: 16 coalesced V-slice loads, weighted sum
    float vv[DEG];
#pragma unroll
    for (int d = 0; d < DEG; d++) {
        int s = __shfl_sync(FULL, nb_l, d);
        vv[d] = V[(size_t)s * HIDD + h * DH + lane];
    }
    float acc = 0.f;
#pragma unroll
    for (int d = 0; d < DEG; d++) {
        float wd = __shfl_sync(FULL, w, d);
        acc = fmaf(wd, vv[d], acc);
    }
    outp[(size_t)n * HIDD + h * DH + lane] = acc;
}

// ---------------- residual + LayerNorm (warp per row, 256-wide rows) -------
__global__ __launch_bounds__(256) void ln_res_kernel(
    const float* __restrict__ y,
    const float* __restrict__ res,
    const float* __restrict__ lg,
    const float* __restrict__ lb,
    float* __restrict__ out)
{
    const int warp = threadIdx.x >> 5, lane = threadIdx.x & 31;
    const int row = blockIdx.x * 8 + warp;
    const float4* yp = (const float4*)(y   + (size_t)row * HIDD);
    const float4* rp = (const float4*)(res + (size_t)row * HIDD);

    float4 v0 = yp[lane],      r0 = rp[lane];
    float4 v1 = yp[lane + 32], r1 = rp[lane + 32];
    v0.x += r0.x; v0.y += r0.y; v0.z += r0.z; v0.w += r0.w;
    v1.x += r1.x; v1.y += r1.y; v1.z += r1.z; v1.w += r1.w;

    float s  = v0.x + v0.y + v0.z + v0.w + v1.x + v1.y + v1.z + v1.w;
    float s2 = v0.x*v0.x + v0.y*v0.y + v0.z*v0.z + v0.w*v0.w
             + v1.x*v1.x + v1.y*v1.y + v1.z*v1.z + v1.w*v1.w;
#pragma unroll
    for (int o = 16; o; o >>= 1) {
        s  += __shfl_xor_sync(0xffffffffu, s,  o);
        s2 += __shfl_xor_sync(0xffffffffu, s2, o);
    }
    const float mu = s * (1.f / 256.f);
    const float var = fmaxf(s2 * (1.f / 256.f) - mu * mu, 0.f);
    const float rs = rsqrtf(var + 1e-5f);

    const float4* gp = (const float4*)lg;
    const float4* bp = (const float4*)lb;
    float4 g0 = gp[lane], g1 = gp[lane + 32];
    float4 b0 = bp[lane], b1 = bp[lane + 32];
    float4 o0, o1;
    o0.x = (v0.x - mu) * rs * g0.x + b0.x;  o0.y = (v0.y - mu) * rs * g0.y + b0.y;
    o0.z = (v0.z - mu) * rs * g0.z + b0.z;  o0.w = (v0.w - mu) * rs * g0.w + b0.w;
    o1.x = (v1.x - mu) * rs * g1.x + b1.x;  o1.y = (v1.y - mu) * rs * g1.y + b1.y;
    o1.z = (v1.z - mu) * rs * g1.z + b1.z;  o1.w = (v1.w - mu) * rs * g1.w + b1.w;
    ((float4*)(out + (size_t)row * HIDD))[lane]      = o0;
    ((float4*)(out + (size_t)row * HIDD))[lane + 32] = o1;
}

// ---------------- launch ----------------
extern "C" void kernel_launch(void* const* d_in, const int* in_sizes, int n_in,
                              void* d_out, int out_size)
{
    const float* x    = (const float*)d_in[0];
    const int*   nb   = (const int*)  d_in[1];
    const float* ef   = (const float*)d_in[2];
    const float* Wq   = (const float*)d_in[3];
    const float* bq   = (const float*)d_in[4];
    const float* Wk   = (const float*)d_in[5];
    const float* bk   = (const float*)d_in[6];
    const float* Wv   = (const float*)d_in[7];
    const float* bv   = (const float*)d_in[8];
    const float* We   = (const float*)d_in[9];
    const float* be   = (const float*)d_in[10];
    const float* Wo   = (const float*)d_in[11];
    const float* bo   = (const float*)d_in[12];
    const float* ln1g = (const float*)d_in[13];
    const float* ln1b = (const float*)d_in[14];
    const float* ln2g = (const float*)d_in[15];
    const float* ln2b = (const float*)d_in[16];
    const float* Wf1  = (const float*)d_in[17];
    const float* bf1  = (const float*)d_in[18];
    const float* Wf2  = (const float*)d_in[19];
    const float* bf2  = (const float*)d_in[20];
    float* out = (float*)d_out;

    float *pQ, *pK, *pV, *pA, *pH1, *pF, *pEA;
    cudaGetSymbolAddress((void**)&pQ,  g_Q);
    cudaGetSymbolAddress((void**)&pK,  g_K);
    cudaGetSymbolAddress((void**)&pV,  g_V);
    cudaGetSymbolAddress((void**)&pA,  g_attn);
    cudaGetSymbolAddress((void**)&pH1, g_h1);
    cudaGetSymbolAddress((void**)&pF,  g_ffn);
    cudaGetSymbolAddress((void**)&pEA, g_ea);

    // edge bias projection (independent of QKV)
    edge_kernel<<<EE / 32, 256>>>(ef, We, be, pEA);

    // fused QKV projection (tf32 tensor cores), one launch
    gemm_qkv<<<dim3(NN / 64, 12), 256>>>(x, Wq, bq, pQ, Wk, bk, pK, Wv, bv, pV);

    // sparse attention, warp per (node, head)
    attn2<<<NN, 256>>>(nb, pEA, be, pQ, pK, pV, pA);

    // Wo (into pK, now free), then residual + LN1 -> h1
    gemm_tc<false><<<dim3(NN / 64, HIDD / 64), 256>>>(pA, Wo, bo, pK, HIDD, HIDD);
    ln_res_kernel<<<NN / 8, 256>>>(pK, x, ln1g, ln1b, pH1);

    // FFN up + ReLU
    gemm_tc<true><<<dim3(NN / 64, FFND / 64), 256>>>(pH1, Wf1, bf1, pF, HIDD, FFND);

    // FFN down (into pQ, free), then residual + LN2 -> out
    gemm_tc<false><<<dim3(NN / 64, HIDD / 64), 256>>>(pF, Wf2, bf2, pQ, FFND, HIDD);
    ln_res_kernel<<<NN / 8, 256>>>(pQ, pH1, ln2g, ln2b, out);
}